// round 6
// baseline (speedup 1.0000x reference)
#include <cuda_runtime.h>
#include <cuda_bf16.h>
#include <stdint.h>

#define NN 16384
#define KDIM 128
#define CAP 64

typedef unsigned long long u64;

// ---------------- scratch (device globals; no dynamic alloc allowed) --------
__device__ int   g_deg[NN];
__device__ int   g_ell[NN * CAP];    // ELL source lists (by target), slot order arbitrary
__device__ float g_agg[NN * KDIM];
__device__ float g_h0[NN * KDIM];
__device__ float g_h1[NN * KDIM];
__device__ float g_xr[NN * KDIM];    // x @ Wr.T partial (reused per layer)

// ---------------- f32x2 packed helpers --------------------------------------
__device__ __forceinline__ void fma2(u64& d, u64 a, u64 b) {
    asm("fma.rn.f32x2 %0, %1, %2, %0;" : "+l"(d) : "l"(a), "l"(b));
}
__device__ __forceinline__ u64 dup2(float w) {
    u64 r;
    asm("mov.b64 %0, {%1, %1};" : "=l"(r) : "f"(w));
    return r;
}
__device__ __forceinline__ void unpack2(u64 v, float& lo, float& hi) {
    asm("mov.b64 {%0, %1}, %2;" : "=f"(lo), "=f"(hi) : "l"(v));
}

// ---------------- init -------------------------------------------------------
__global__ void init_kernel() {
    int i = blockIdx.x * blockDim.x + threadIdx.x;
    if (i < NN) g_deg[i] = 0;
}

// ---------------- pass A: stream adj once, scatter edges straight to ELL -----
// 1024 blocks x 256 threads = 262144 threads; 256 float4/thread, exact division.
__global__ void scan_adj_kernel(const float4* __restrict__ adj4) {
    const int stride = gridDim.x * blockDim.x;   // 262144
    const int tid = blockIdx.x * blockDim.x + threadIdx.x;
#pragma unroll 1
    for (int it = 0; it < 32; it++) {
        int base = tid + it * 8 * stride;
        float4 v[8];
#pragma unroll
        for (int j = 0; j < 8; j++) v[j] = __ldcs(&adj4[base + j * stride]);
#pragma unroll
        for (int j = 0; j < 8; j++) {
            int m = ((__float_as_int(v[j].x) != 0) ? 1 : 0) |
                    ((__float_as_int(v[j].y) != 0) ? 2 : 0) |
                    ((__float_as_int(v[j].z) != 0) ? 4 : 0) |
                    ((__float_as_int(v[j].w) != 0) ? 8 : 0);
            if (__any_sync(0xffffffffu, m != 0)) {
                int e4 = (base + j * stride) * 4;
#pragma unroll
                for (int b = 0; b < 4; b++) {
                    if (m & (1 << b)) {
                        int elem = e4 + b;
                        int c = elem & (NN - 1);      // target node
                        int r = elem >> 14;           // source node
                        int slot = atomicAdd(&g_deg[c], 1);
                        if (slot < CAP) g_ell[c * CAP + slot] = r;
                    }
                }
            }
        }
    }
}

// ---------------- mean aggregation: one warp per 2 target nodes (ELL) -------
// 2-node interleave -> 8 outstanding 512B gathers per warp.
__global__ void aggregate_kernel(const float* __restrict__ xin) {
    int w = (blockIdx.x * blockDim.x + threadIdx.x) >> 5;   // 0..8191
    int lane = threadIdx.x & 31;
    int nA = 2 * w;
    int nB = 2 * w + 1;
    if (nA >= NN) return;
    int dA = min(g_deg[nA], CAP);
    int dB = min(g_deg[nB], CAP);
    const int* __restrict__ srcA = &g_ell[nA * CAP];
    const int* __restrict__ srcB = &g_ell[nB * CAP];
    const float4* __restrict__ x4 = (const float4*)xin;
    float4 aA = make_float4(0.f, 0.f, 0.f, 0.f);
    float4 aB = make_float4(0.f, 0.f, 0.f, 0.f);
    int emax = max(dA, dB);
    for (int e = 0; e < emax; e += 4) {
        float4 vA[4], vB[4];
#pragma unroll
        for (int q = 0; q < 4; q++) {
            vA[q] = make_float4(0.f, 0.f, 0.f, 0.f);
            vB[q] = make_float4(0.f, 0.f, 0.f, 0.f);
            if (e + q < dA) vA[q] = __ldg(&x4[__ldg(&srcA[e + q]) * 32 + lane]);
            if (e + q < dB) vB[q] = __ldg(&x4[__ldg(&srcB[e + q]) * 32 + lane]);
        }
#pragma unroll
        for (int q = 0; q < 4; q++) {
            aA.x += vA[q].x; aA.y += vA[q].y; aA.z += vA[q].z; aA.w += vA[q].w;
            aB.x += vB[q].x; aB.y += vB[q].y; aB.z += vB[q].z; aB.w += vB[q].w;
        }
    }
    float iA = (dA > 0) ? (1.0f / (float)dA) : 0.0f;
    float iB = (dB > 0) ? (1.0f / (float)dB) : 0.0f;
    ((float4*)g_agg)[nA * 32 + lane] =
        make_float4(aA.x * iA, aA.y * iA, aA.z * iA, aA.w * iA);
    ((float4*)g_agg)[nB * 32 + lane] =
        make_float4(aB.x * iB, aB.y * iB, aB.z * iB, aB.w * iB);
}

// ---------------- single GEMM: out = A @ W.T  (+ b + XR, optional relu) -----
// A tile (64 nodes x full K=128) resident in swizzled smem, loaded once.
// Node-paired f32x2, broadcast W via dup2. Block: 64 nodes x 64 outputs.
// EPI 0: plain store (XR pass).  EPI 1: + b + XR, relu.  EPI 2: + b + XR.
template <int FO, int EPI>
__global__ __launch_bounds__(256) void sgemm_kernel(
    const float* __restrict__ A, const float* __restrict__ W,
    const float* __restrict__ b, const float* __restrict__ XR,
    float* __restrict__ out) {
    constexpr int KC = 16;
    constexpr int NT = 64;
    constexpr int FOB = 64;
    constexpr int FJ = FOB / 16;         // 4
    __shared__ float sA[KDIM * NT];      // [k][n] with phys_n = n ^ (2*((k>>2)&15))
    __shared__ float sW[KC][FOB + 4];

    const int tid = threadIdx.x;
    const int tx = tid & 15;             // f = fb + tx + 16*j
    const int ty = tid >> 4;             // n0 = 4*ty
    const int n0 = ty * 4;
    const int nb = blockIdx.x * NT;
    const int fb = blockIdx.y * FOB;

    // load whole A tile (64 nodes x 128 k), swizzled
    {
        int n = tid & 63;
        int cbase = tid >> 6;            // 0..3
#pragma unroll
        for (int i = 0; i < 8; i++) {
            int c = cbase + 4 * i;       // float4 column, 0..31
            float4 v = *(const float4*)&A[(nb + n) * KDIM + 4 * c];
            int phys = n ^ (2 * (c & 15));
            sA[(4 * c + 0) * NT + phys] = v.x;
            sA[(4 * c + 1) * NT + phys] = v.y;
            sA[(4 * c + 2) * NT + phys] = v.z;
            sA[(4 * c + 3) * NT + phys] = v.w;
        }
    }

    u64 acc[2][FJ];
#pragma unroll
    for (int p = 0; p < 2; p++)
#pragma unroll
        for (int j = 0; j < FJ; j++) acc[p][j] = 0ull;

    for (int kc0 = 0; kc0 < KDIM; kc0 += KC) {
        {   // W chunk: 64 f-rows x 16 k
            int f = tid >> 2;
            int kq = (tid & 3) * 4;
            float4 wv = *(const float4*)&W[(fb + f) * KDIM + kc0 + kq];
            sW[kq + 0][f] = wv.x; sW[kq + 1][f] = wv.y;
            sW[kq + 2][f] = wv.z; sW[kq + 3][f] = wv.w;
        }
        __syncthreads();

#pragma unroll
        for (int kk = 0; kk < KC; kk++) {
            int k = kc0 + kk;
            int sw = 2 * ((k >> 2) & 15);
            const float* base = &sA[k * NT];
            u64 a0 = *reinterpret_cast<const u64*>(&base[n0 ^ sw]);
            u64 a1 = *reinterpret_cast<const u64*>(&base[(n0 + 2) ^ sw]);
#pragma unroll
            for (int j = 0; j < FJ; j++) {
                u64 w2 = dup2(sW[kk][tx + 16 * j]);
                fma2(acc[0][j], a0, w2);
                fma2(acc[1][j], a1, w2);
            }
        }
        __syncthreads();
    }

#pragma unroll
    for (int j = 0; j < FJ; j++) {
        int f = fb + tx + 16 * j;
        float bv = (EPI != 0) ? __ldg(&b[f]) : 0.0f;
#pragma unroll
        for (int p = 0; p < 2; p++) {
            float lo, hi;
            unpack2(acc[p][j], lo, hi);
            int n = nb + n0 + 2 * p;
            if (EPI != 0) {
                lo += bv + __ldg(&XR[n * FO + f]);
                hi += bv + __ldg(&XR[(n + 1) * FO + f]);
                if (EPI == 1) { lo = fmaxf(lo, 0.f); hi = fmaxf(hi, 0.f); }
            }
            out[n * FO + f] = lo;
            out[(n + 1) * FO + f] = hi;
        }
    }
}

// ---------------- launch -----------------------------------------------------
extern "C" void kernel_launch(void* const* d_in, const int* in_sizes, int n_in,
                              void* d_out, int out_size) {
    const float* x   = (const float*)d_in[0];
    const float* adj = (const float*)d_in[1];
    const float* Wl0 = (const float*)d_in[2];
    const float* b0  = (const float*)d_in[3];
    const float* Wr0 = (const float*)d_in[4];
    const float* Wl1 = (const float*)d_in[5];
    const float* b1  = (const float*)d_in[6];
    const float* Wr1 = (const float*)d_in[7];
    const float* Wl2 = (const float*)d_in[8];
    const float* b2  = (const float*)d_in[9];
    const float* Wr2 = (const float*)d_in[10];
    float* out = (float*)d_out;

    float *p_agg, *p_h0, *p_h1, *p_xr;
    cudaGetSymbolAddress((void**)&p_agg, g_agg);
    cudaGetSymbolAddress((void**)&p_h0, g_h0);
    cudaGetSymbolAddress((void**)&p_h1, g_h1);
    cudaGetSymbolAddress((void**)&p_xr, g_xr);

    // side stream + events (created once on first, non-captured call; the
    // sequence of launched work is identical on every call)
    static cudaStream_t s2 = nullptr;
    static cudaEvent_t evF0, evX0, evF1, evX1, evF2, evX2;
    if (s2 == nullptr) {
        cudaStreamCreateWithFlags(&s2, cudaStreamNonBlocking);
        cudaEventCreateWithFlags(&evF0, cudaEventDisableTiming);
        cudaEventCreateWithFlags(&evX0, cudaEventDisableTiming);
        cudaEventCreateWithFlags(&evF1, cudaEventDisableTiming);
        cudaEventCreateWithFlags(&evX1, cudaEventDisableTiming);
        cudaEventCreateWithFlags(&evF2, cudaEventDisableTiming);
        cudaEventCreateWithFlags(&evX2, cudaEventDisableTiming);
    }

    dim3 g128(256, 2);   // FO=128: 256 node-tiles x 2 f-blocks
    dim3 g64(256, 1);    // FO=64

    init_kernel<<<64, 256>>>();

    // fork: XR0 = x @ Wr0.T on s2, overlapping the adj scan
    cudaEventRecord(evF0, 0);
    cudaStreamWaitEvent(s2, evF0, 0);
    sgemm_kernel<128, 0><<<g128, 256, 0, s2>>>(x, Wr0, nullptr, nullptr, p_xr);
    cudaEventRecord(evX0, s2);

    scan_adj_kernel<<<1024, 256>>>((const float4*)adj);

    // layer 0
    aggregate_kernel<<<1024, 256>>>(x);
    cudaStreamWaitEvent(0, evX0, 0);
    sgemm_kernel<128, 1><<<g128, 256>>>(p_agg, Wl0, b0, p_xr, p_h0);

    // layer 1: XR1 = h0 @ Wr1.T on s2, overlapping aggregate(h0)
    cudaEventRecord(evF1, 0);
    cudaStreamWaitEvent(s2, evF1, 0);
    sgemm_kernel<128, 0><<<g128, 256, 0, s2>>>(p_h0, Wr1, nullptr, nullptr, p_xr);
    cudaEventRecord(evX1, s2);
    aggregate_kernel<<<1024, 256>>>(p_h0);
    cudaStreamWaitEvent(0, evX1, 0);
    sgemm_kernel<128, 1><<<g128, 256>>>(p_agg, Wl1, b1, p_xr, p_h1);

    // layer 2: XR2 = h1 @ Wr2.T on s2, overlapping aggregate(h1)
    cudaEventRecord(evF2, 0);
    cudaStreamWaitEvent(s2, evF2, 0);
    sgemm_kernel<64, 0><<<g64, 256, 0, s2>>>(p_h1, Wr2, nullptr, nullptr, p_xr);
    cudaEventRecord(evX2, s2);
    aggregate_kernel<<<1024, 256>>>(p_h1);
    cudaStreamWaitEvent(0, evX2, 0);
    sgemm_kernel<64, 2><<<g64, 256>>>(p_agg, Wl2, b2, p_xr, out);
}

// round 7
// speedup vs baseline: 1.2318x; 1.2318x over previous
#include <cuda_runtime.h>
#include <cuda_bf16.h>
#include <stdint.h>

#define NN 16384
#define KDIM 128
#define CAP 64

typedef unsigned long long u64;

// ---------------- scratch (device globals; no dynamic alloc allowed) --------
__device__ int   g_deg[NN];
__device__ int   g_ell[NN * CAP];    // ELL source lists (by target), slot order arbitrary
__device__ float g_agg[NN * KDIM];
__device__ float g_h0[NN * KDIM];
__device__ float g_h1[NN * KDIM];
__device__ float g_xr[NN * KDIM];    // x @ Wr.T partial (reused per layer)

// ---------------- f32x2 packed helpers --------------------------------------
__device__ __forceinline__ void fma2(u64& d, u64 a, u64 b) {
    asm("fma.rn.f32x2 %0, %1, %2, %0;" : "+l"(d) : "l"(a), "l"(b));
}
__device__ __forceinline__ u64 dup2(float w) {
    u64 r;
    asm("mov.b64 %0, {%1, %1};" : "=l"(r) : "f"(w));
    return r;
}
__device__ __forceinline__ void unpack2(u64 v, float& lo, float& hi) {
    asm("mov.b64 {%0, %1}, %2;" : "=f"(lo), "=f"(hi) : "l"(v));
}

// ---------------- init -------------------------------------------------------
__global__ void init_kernel() {
    int i = blockIdx.x * blockDim.x + threadIdx.x;
    if (i < NN) g_deg[i] = 0;
}

// ---------------- pass A: stream adj once, scatter edges straight to ELL -----
// 1024 blocks x 256 threads = 262144 threads; 256 float4/thread, exact division.
__global__ void scan_adj_kernel(const float4* __restrict__ adj4) {
    const int stride = gridDim.x * blockDim.x;   // 262144
    const int tid = blockIdx.x * blockDim.x + threadIdx.x;
#pragma unroll 1
    for (int it = 0; it < 32; it++) {
        int base = tid + it * 8 * stride;
        float4 v[8];
#pragma unroll
        for (int j = 0; j < 8; j++) v[j] = __ldcs(&adj4[base + j * stride]);
#pragma unroll
        for (int j = 0; j < 8; j++) {
            int m = ((__float_as_int(v[j].x) != 0) ? 1 : 0) |
                    ((__float_as_int(v[j].y) != 0) ? 2 : 0) |
                    ((__float_as_int(v[j].z) != 0) ? 4 : 0) |
                    ((__float_as_int(v[j].w) != 0) ? 8 : 0);
            if (__any_sync(0xffffffffu, m != 0)) {
                int e4 = (base + j * stride) * 4;
#pragma unroll
                for (int b = 0; b < 4; b++) {
                    if (m & (1 << b)) {
                        int elem = e4 + b;
                        int c = elem & (NN - 1);      // target node
                        int r = elem >> 14;           // source node
                        int slot = atomicAdd(&g_deg[c], 1);
                        if (slot < CAP) g_ell[c * CAP + slot] = r;
                    }
                }
            }
        }
    }
}

// ---------------- mean aggregation: one warp per 2 target nodes (ELL) -------
// 2-node interleave -> 8 outstanding 512B gathers per warp.
__global__ void aggregate_kernel(const float* __restrict__ xin) {
    int w = (blockIdx.x * blockDim.x + threadIdx.x) >> 5;   // 0..8191
    int lane = threadIdx.x & 31;
    int nA = 2 * w;
    int nB = 2 * w + 1;
    if (nA >= NN) return;
    int dA = min(g_deg[nA], CAP);
    int dB = min(g_deg[nB], CAP);
    const int* __restrict__ srcA = &g_ell[nA * CAP];
    const int* __restrict__ srcB = &g_ell[nB * CAP];
    const float4* __restrict__ x4 = (const float4*)xin;
    float4 aA = make_float4(0.f, 0.f, 0.f, 0.f);
    float4 aB = make_float4(0.f, 0.f, 0.f, 0.f);
    int emax = max(dA, dB);
    for (int e = 0; e < emax; e += 4) {
        float4 vA[4], vB[4];
#pragma unroll
        for (int q = 0; q < 4; q++) {
            vA[q] = make_float4(0.f, 0.f, 0.f, 0.f);
            vB[q] = make_float4(0.f, 0.f, 0.f, 0.f);
            if (e + q < dA) vA[q] = __ldg(&x4[__ldg(&srcA[e + q]) * 32 + lane]);
            if (e + q < dB) vB[q] = __ldg(&x4[__ldg(&srcB[e + q]) * 32 + lane]);
        }
#pragma unroll
        for (int q = 0; q < 4; q++) {
            aA.x += vA[q].x; aA.y += vA[q].y; aA.z += vA[q].z; aA.w += vA[q].w;
            aB.x += vB[q].x; aB.y += vB[q].y; aB.z += vB[q].z; aB.w += vB[q].w;
        }
    }
    float iA = (dA > 0) ? (1.0f / (float)dA) : 0.0f;
    float iB = (dB > 0) ? (1.0f / (float)dB) : 0.0f;
    ((float4*)g_agg)[nA * 32 + lane] =
        make_float4(aA.x * iA, aA.y * iA, aA.z * iA, aA.w * iA);
    ((float4*)g_agg)[nB * 32 + lane] =
        make_float4(aB.x * iB, aB.y * iB, aB.z * iB, aB.w * iB);
}

// ---------------- single GEMM: out = A @ W.T  (+ b + XR, optional relu) -----
// Node-paired f32x2 (broadcast W), 128 nodes x 64 outputs per block.
// EPI 0: plain store (XR pass).  EPI 1: + b + XR, relu.  EPI 2: + b + XR.
template <int FO, int EPI>
__global__ __launch_bounds__(256, 4) void sgemm_kernel(
    const float* __restrict__ A, const float* __restrict__ W,
    const float* __restrict__ b, const float* __restrict__ XR,
    float* __restrict__ out) {
    constexpr int KC = 16;
    constexpr int FOB = 64;
    constexpr int FJ = FOB / 16;         // 4
    __shared__ float sA[KC][132];
    __shared__ float sW[KC][FOB + 4];

    const int tid = threadIdx.x;
    const int tx = tid & 15;             // f = fb + tx + 16*j
    const int ty = tid >> 4;             // n0 = ty*8
    const int n0 = ty * 8;
    const int nb = blockIdx.x * 128;
    const int fb = blockIdx.y * FOB;

    u64 acc[4][FJ];
#pragma unroll
    for (int p = 0; p < 4; p++)
#pragma unroll
        for (int j = 0; j < FJ; j++) acc[p][j] = 0ull;

    const int kq = (tid & 3) * 4;
    const int rr = tid >> 2;             // 0..63

    for (int kc0 = 0; kc0 < KDIM; kc0 += KC) {
#pragma unroll
        for (int h = 0; h < 2; h++) {
            int n = rr + h * 64;
            float4 va = *(const float4*)&A[(nb + n) * KDIM + kc0 + kq];
            sA[kq + 0][n] = va.x; sA[kq + 1][n] = va.y;
            sA[kq + 2][n] = va.z; sA[kq + 3][n] = va.w;
        }
        {
            int f = rr;
            float4 wv = *(const float4*)&W[(fb + f) * KDIM + kc0 + kq];
            sW[kq + 0][f] = wv.x; sW[kq + 1][f] = wv.y;
            sW[kq + 2][f] = wv.z; sW[kq + 3][f] = wv.w;
        }
        __syncthreads();

#pragma unroll 4
        for (int kk = 0; kk < KC; kk++) {
            const u64* pa = reinterpret_cast<const u64*>(&sA[kk][n0]);
            u64 a[4];
#pragma unroll
            for (int p = 0; p < 4; p++) a[p] = pa[p];
#pragma unroll
            for (int j = 0; j < FJ; j++) {
                u64 w2 = dup2(sW[kk][tx + 16 * j]);
#pragma unroll
                for (int p = 0; p < 4; p++) fma2(acc[p][j], a[p], w2);
            }
        }
        __syncthreads();
    }

#pragma unroll
    for (int j = 0; j < FJ; j++) {
        int f = fb + tx + 16 * j;
        float bv = (EPI != 0) ? __ldg(&b[f]) : 0.0f;
#pragma unroll
        for (int p = 0; p < 4; p++) {
            float lo, hi;
            unpack2(acc[p][j], lo, hi);
            int n = nb + n0 + 2 * p;
            if (EPI != 0) {
                lo += bv + __ldg(&XR[n * FO + f]);
                hi += bv + __ldg(&XR[(n + 1) * FO + f]);
                if (EPI == 1) { lo = fmaxf(lo, 0.f); hi = fmaxf(hi, 0.f); }
            }
            out[n * FO + f] = lo;
            out[(n + 1) * FO + f] = hi;
        }
    }
}

// ---------------- launch -----------------------------------------------------
extern "C" void kernel_launch(void* const* d_in, const int* in_sizes, int n_in,
                              void* d_out, int out_size) {
    const float* x   = (const float*)d_in[0];
    const float* adj = (const float*)d_in[1];
    const float* Wl0 = (const float*)d_in[2];
    const float* b0  = (const float*)d_in[3];
    const float* Wr0 = (const float*)d_in[4];
    const float* Wl1 = (const float*)d_in[5];
    const float* b1  = (const float*)d_in[6];
    const float* Wr1 = (const float*)d_in[7];
    const float* Wl2 = (const float*)d_in[8];
    const float* b2  = (const float*)d_in[9];
    const float* Wr2 = (const float*)d_in[10];
    float* out = (float*)d_out;

    float *p_agg, *p_h0, *p_h1, *p_xr;
    cudaGetSymbolAddress((void**)&p_agg, g_agg);
    cudaGetSymbolAddress((void**)&p_h0, g_h0);
    cudaGetSymbolAddress((void**)&p_h1, g_h1);
    cudaGetSymbolAddress((void**)&p_xr, g_xr);

    // side stream + events (created once on first, non-captured call; the
    // sequence of launched work is identical on every call)
    static cudaStream_t s2 = nullptr;
    static cudaEvent_t evF0, evX0, evF1, evX1, evF2, evX2;
    if (s2 == nullptr) {
        cudaStreamCreateWithFlags(&s2, cudaStreamNonBlocking);
        cudaEventCreateWithFlags(&evF0, cudaEventDisableTiming);
        cudaEventCreateWithFlags(&evX0, cudaEventDisableTiming);
        cudaEventCreateWithFlags(&evF1, cudaEventDisableTiming);
        cudaEventCreateWithFlags(&evX1, cudaEventDisableTiming);
        cudaEventCreateWithFlags(&evF2, cudaEventDisableTiming);
        cudaEventCreateWithFlags(&evX2, cudaEventDisableTiming);
    }

    dim3 g128(128, 2);   // FO=128
    dim3 g64(128, 1);    // FO=64

    init_kernel<<<64, 256>>>();

    // fork: XR0 = x @ Wr0.T on s2, overlapping the adj scan
    cudaEventRecord(evF0, 0);
    cudaStreamWaitEvent(s2, evF0, 0);
    sgemm_kernel<128, 0><<<g128, 256, 0, s2>>>(x, Wr0, nullptr, nullptr, p_xr);
    cudaEventRecord(evX0, s2);

    scan_adj_kernel<<<1024, 256>>>((const float4*)adj);

    // layer 0
    aggregate_kernel<<<1024, 256>>>(x);
    cudaStreamWaitEvent(0, evX0, 0);
    sgemm_kernel<128, 1><<<g128, 256>>>(p_agg, Wl0, b0, p_xr, p_h0);

    // layer 1: XR1 = h0 @ Wr1.T on s2, overlapping aggregate(h0)
    cudaEventRecord(evF1, 0);
    cudaStreamWaitEvent(s2, evF1, 0);
    sgemm_kernel<128, 0><<<g128, 256, 0, s2>>>(p_h0, Wr1, nullptr, nullptr, p_xr);
    cudaEventRecord(evX1, s2);
    aggregate_kernel<<<1024, 256>>>(p_h0);
    cudaStreamWaitEvent(0, evX1, 0);
    sgemm_kernel<128, 1><<<g128, 256>>>(p_agg, Wl1, b1, p_xr, p_h1);

    // layer 2: XR2 = h1 @ Wr2.T on s2, overlapping aggregate(h1)
    cudaEventRecord(evF2, 0);
    cudaStreamWaitEvent(s2, evF2, 0);
    sgemm_kernel<64, 0><<<g64, 256, 0, s2>>>(p_h1, Wr2, nullptr, nullptr, p_xr);
    cudaEventRecord(evX2, s2);
    aggregate_kernel<<<1024, 256>>>(p_h1);
    cudaStreamWaitEvent(0, evX2, 0);
    sgemm_kernel<64, 2><<<g64, 256>>>(p_agg, Wl2, b2, p_xr, out);
}